// round 4
// baseline (speedup 1.0000x reference)
#include <cuda_runtime.h>
#include <cstdint>

// HIRNN (GR4J-style) forward, fma-pipe-minimized form.
// Per-warp bottleneck is the fma pipe (rt_SMSP=2) at 1 warp/SM, so every fma
// instruction removed is ~2 cycles/step. This version: 18 fma + 6 alu + 1 mufu
// per step (was 23 fma).
//
// Key identities (all exact away from <=1e-6 heaviside ties):
//  - heaviside pairs == min/max
//  - GW >= 0 by induction  =>  BAS = RecK*GW,  GW' = (1-RecK)*GW + RECn
//  - max(s-1,0) == s - min(s,1); min(s,1) also feeds the u-clamp (alu pipe)
//  - q = SUB*w + (INR-RMO) + RecK*GW  as a 3-FFMA chain (no separate BAS)
// clip(+-1e5) provably inactive. State normalized: u = SMS/SMSC in [0,1].
//
// Q[t] (t>=1) uses the pre-step state at t  -> computed inside the loop.
// Q[0] uses the FINAL state (roll shift=1)  -> recomputed after the loop.

__device__ __forceinline__ float ex2f(float x) {
    float y;
    asm("ex2.approx.f32 %0, %1;" : "=f"(y) : "f"(x));
    return y;
}

struct Params {
    float INSC, SMSC, SUB, CRAK, RecK, alpha, ivS, ck2, lC, nSUB, nCRbi;
};

// One step: advances (u, GW); returns Q computed from the PRE-step state.
__device__ __forceinline__ float stepq(float Prec, float PET,
                                       float& u, float& GW, const Params& p)
{
    // interception (state-independent, starts immediately)
    float INTm = fminf(PET, Prec);             // alu
    float INT  = fminf(p.INSC, INTm);          // alu
    float INR  = Prec - INT;                   // fma
    float POT  = PET - INT;                    // fma

    // ---- critical chain: FFMA -> MUFU -> FMNMX -> FFMA(s) -> FMNMX clamp ----
    float arg = fmaf(p.ck2, u, p.lC);          // fma
    float cap = ex2f(arg);                     // mufu: COEFF*exp(-SQ*u)
    float RMO = fminf(cap, INR);               // alu

    // ---- off-chain state polynomials (overlap with MUFU) ----
    float t10  = u * 10.0f;                    // fma (imm mult)
    float m    = fminf(t10, POT);              // alu
    float base = fmaf(-p.ivS, m, u);           // fma : u - ETS/SMSC
    float a    = fmaf(p.nSUB,  u, 1.0f);       // fma : 1 - SUB*u
    float bi   = fmaf(p.nCRbi, u, p.ivS);      // fma : (1 - CRAK*u)/SMSC
    float fi   = a * bi;                       // fma
    float w    = u * RMO;                      // fma

    float s    = fmaf(RMO, fi, base);          // fma : pre-clamp next u
    float umid = fminf(s, 1.0f);               // alu
    float u_n  = fmaxf(umid, 0.0f);            // alu : next u
    float ov   = s - umid;                     // fma : == max(s-1,0)

    // ---- recharge / groundwater / discharge ----
    float cw   = p.CRAK * w;                   // fma
    float REC  = cw * a;                       // fma
    float RECn = fmaf(p.SMSC, ov, REC);        // fma
    float dq   = INR - RMO;                    // fma
    float t1   = fmaf(p.RecK, GW, dq);         // fma : IRUN + BAS
    float q    = fmaf(p.SUB,  w,  t1);         // fma : + SRUN

    GW = fmaf(p.alpha, GW, RECn);              // fma : (1-RecK)*GW + RECn
    u  = u_n;
    return q;
}

template <int T>
__global__ void hirnn_kernel(const float* __restrict__ in,
                             const float* __restrict__ pINSC,
                             const float* __restrict__ pCOEFF,
                             const float* __restrict__ pSQ,
                             const float* __restrict__ pSMSC,
                             const float* __restrict__ pSUB,
                             const float* __restrict__ pCRAK,
                             const float* __restrict__ pRecK,
                             float* __restrict__ out, int B)
{
    int bidx = blockIdx.x * 32 + threadIdx.x;
    if (bidx >= B) return;

    Params p;
    p.INSC   = fminf(fmaxf(pINSC[0]  * 5.f,   0.5f),   5.f);
    float CO = fminf(fmaxf(pCOEFF[0] * 400.f, 50.f),   400.f);
    float SQ = fminf(fmaxf(pSQ[0]    * 6.f,   0.f),    6.f);
    p.SMSC   = fminf(fmaxf(pSMSC[0]  * 500.f, 50.f),   500.f);
    p.SUB    = fminf(fmaxf(pSUB[0],           0.f),    1.f);
    p.CRAK   = fminf(fmaxf(pCRAK[0],          0.f),    1.f);
    p.RecK   = fminf(fmaxf(pRecK[0]  * 0.3f,  0.003f), 0.3f);
    p.alpha  = 1.f - p.RecK;
    p.ivS    = 1.f / p.SMSC;
    p.ck2    = -SQ * 1.44269504088896340736f;   // -SQ*log2(e), arg in u-units
    p.lC     = __log2f(CO);
    p.nSUB   = -p.SUB;
    p.nCRbi  = -p.CRAK * p.ivS;

    const float4* row  = reinterpret_cast<const float4*>(in + (size_t)bidx * T * 2);
    float4*       orow = reinterpret_cast<float4*>(out + (size_t)bidx * T);

    float u = 0.f, GW = 0.f;

    // peel inputs of t=0 for the final Q[0] fixup
    float4 f0 = __ldg(&row[0]);
    float Prec0 = f0.x, PET0 = f0.y;

    #pragma unroll 2
    for (int i = 0; i < T / 4; ++i) {
        float4 v0 = __ldg(&row[2 * i]);
        float4 v1 = __ldg(&row[2 * i + 1]);
        float4 q;
        q.x = stepq(v0.x, v0.y, u, GW, p);
        q.y = stepq(v0.z, v0.w, u, GW, p);
        q.z = stepq(v1.x, v1.y, u, GW, p);
        q.w = stepq(v1.z, v1.w, u, GW, p);
        orow[i] = q;   // q.x at i==0 is a placeholder, overwritten below
    }

    // Q[0]: roll(shift=1) puts the FINAL state at t=0.
    float u2 = u, G2 = GW;
    float q0 = stepq(Prec0, PET0, u2, G2, p);
    out[(size_t)bidx * T] = q0;
}

extern "C" void kernel_launch(void* const* d_in, const int* in_sizes, int n_in,
                              void* d_out, int out_size)
{
    const float* in    = (const float*)d_in[0];
    const float* INSC  = (const float*)d_in[1];
    const float* COEFF = (const float*)d_in[2];
    const float* SQ    = (const float*)d_in[3];
    const float* SMSC  = (const float*)d_in[4];
    const float* SUB   = (const float*)d_in[5];
    const float* CRAK  = (const float*)d_in[6];
    const float* RecK  = (const float*)d_in[7];
    float* out = (float*)d_out;

    constexpr int T = 1024;
    int B = out_size / T;
    int blocks = (B + 31) / 32;
    hirnn_kernel<T><<<blocks, 32>>>(in, INSC, COEFF, SQ, SMSC, SUB, CRAK, RecK,
                                    out, B);
}

// round 5
// speedup vs baseline: 1.5465x; 1.5465x over previous
#include <cuda_runtime.h>
#include <cstdint>

// HIRNN (GR4J-style) forward.
// R5 = R4's op-minimized step (18 fma + 6 alu + 1 mufu) + R3's scheduling
// regime restored: __launch_bounds__(32,1) so ptxas takes a big reg budget
// (R4 showed that dropping to 32 regs kills cross-step pipelining: 54->87us).
//
// Key identities (exact away from <=1e-6 heaviside ties):
//  - heaviside select pairs == min/max
//  - GW >= 0 by induction  =>  BAS = RecK*GW,  GW' = (1-RecK)*GW + RECn
//  - max(s-1,0) == s - min(s,1); min(s,1) also feeds the u-clamp
//  - q = SUB*w + (INR-RMO) + RecK*GW as a 3-FFMA chain
// clip(+-1e5) provably inactive. State normalized: u = SMS/SMSC in [0,1].
//
// Q[t] (t>=1) uses the pre-step state at t  -> computed inside the loop.
// Q[0] uses the FINAL state (roll shift=1)  -> recomputed after the loop.

__device__ __forceinline__ float ex2f(float x) {
    float y;
    asm("ex2.approx.f32 %0, %1;" : "=f"(y) : "f"(x));
    return y;
}

struct Params {
    float INSC, SMSC, SUB, CRAK, RecK, alpha, ivS, ck2, lC, nSUB, nCRbi;
};

// One step: advances (u, GW); returns Q computed from the PRE-step state.
__device__ __forceinline__ float stepq(float Prec, float PET,
                                       float& u, float& GW, const Params& p)
{
    // interception (state-independent, starts immediately)
    float INTm = fminf(PET, Prec);             // alu
    float INT  = fminf(p.INSC, INTm);          // alu
    float INR  = Prec - INT;                   // fma
    float POT  = PET - INT;                    // fma

    // ---- critical chain: FFMA -> MUFU -> FMNMX -> FFMA(s) -> clamp ----
    float arg = fmaf(p.ck2, u, p.lC);          // fma
    float cap = ex2f(arg);                     // mufu: COEFF*exp(-SQ*u)
    float RMO = fminf(cap, INR);               // alu

    // ---- off-chain state polynomials (overlap with MUFU) ----
    float t10  = u * 10.0f;                    // fma (imm)
    float m    = fminf(t10, POT);              // alu
    float base = fmaf(-p.ivS, m, u);           // fma : u - ETS/SMSC
    float a    = fmaf(p.nSUB,  u, 1.0f);       // fma : 1 - SUB*u
    float bi   = fmaf(p.nCRbi, u, p.ivS);      // fma : (1 - CRAK*u)/SMSC
    float fi   = a * bi;                       // fma
    float w    = u * RMO;                      // fma

    float s    = fmaf(RMO, fi, base);          // fma : pre-clamp next u
    float umid = fminf(s, 1.0f);               // alu
    float u_n  = fmaxf(umid, 0.0f);            // alu : next u
    float ov   = s - umid;                     // fma : == max(s-1,0)

    // ---- recharge / groundwater / discharge (off-chain tail) ----
    float cw   = p.CRAK * w;                   // fma
    float REC  = cw * a;                       // fma
    float RECn = fmaf(p.SMSC, ov, REC);        // fma
    float dq   = INR - RMO;                    // fma
    float t1   = fmaf(p.RecK, GW, dq);         // fma : IRUN + BAS
    float q    = fmaf(p.SUB,  w,  t1);         // fma : + SRUN

    GW = fmaf(p.alpha, GW, RECn);              // fma : (1-RecK)*GW + RECn
    u  = u_n;
    return q;
}

template <int T>
__global__ __launch_bounds__(32, 1)
void hirnn_kernel(const float* __restrict__ in,
                  const float* __restrict__ pINSC,
                  const float* __restrict__ pCOEFF,
                  const float* __restrict__ pSQ,
                  const float* __restrict__ pSMSC,
                  const float* __restrict__ pSUB,
                  const float* __restrict__ pCRAK,
                  const float* __restrict__ pRecK,
                  float* __restrict__ out, int B)
{
    int bidx = blockIdx.x * 32 + threadIdx.x;
    if (bidx >= B) return;

    Params p;
    p.INSC   = fminf(fmaxf(pINSC[0]  * 5.f,   0.5f),   5.f);
    float CO = fminf(fmaxf(pCOEFF[0] * 400.f, 50.f),   400.f);
    float SQ = fminf(fmaxf(pSQ[0]    * 6.f,   0.f),    6.f);
    p.SMSC   = fminf(fmaxf(pSMSC[0]  * 500.f, 50.f),   500.f);
    p.SUB    = fminf(fmaxf(pSUB[0],           0.f),    1.f);
    p.CRAK   = fminf(fmaxf(pCRAK[0],          0.f),    1.f);
    p.RecK   = fminf(fmaxf(pRecK[0]  * 0.3f,  0.003f), 0.3f);
    p.alpha  = 1.f - p.RecK;
    p.ivS    = 1.f / p.SMSC;
    p.ck2    = -SQ * 1.44269504088896340736f;   // -SQ*log2(e), arg in u-units
    p.lC     = __log2f(CO);
    p.nSUB   = -p.SUB;
    p.nCRbi  = -p.CRAK * p.ivS;

    const float4* row  = reinterpret_cast<const float4*>(in + (size_t)bidx * T * 2);
    float4*       orow = reinterpret_cast<float4*>(out + (size_t)bidx * T);

    float u = 0.f, GW = 0.f;

    // peel inputs of t=0 for the final Q[0] fixup
    float4 f0 = __ldg(&row[0]);
    float Prec0 = f0.x, PET0 = f0.y;

    #pragma unroll 4
    for (int i = 0; i < T / 4; ++i) {
        float4 v0 = __ldg(&row[2 * i]);
        float4 v1 = __ldg(&row[2 * i + 1]);
        float4 q;
        q.x = stepq(v0.x, v0.y, u, GW, p);
        q.y = stepq(v0.z, v0.w, u, GW, p);
        q.z = stepq(v1.x, v1.y, u, GW, p);
        q.w = stepq(v1.z, v1.w, u, GW, p);
        orow[i] = q;   // q.x at i==0 is a placeholder, overwritten below
    }

    // Q[0]: roll(shift=1) puts the FINAL state at t=0.
    float u2 = u, G2 = GW;
    float q0 = stepq(Prec0, PET0, u2, G2, p);
    out[(size_t)bidx * T] = q0;
}

extern "C" void kernel_launch(void* const* d_in, const int* in_sizes, int n_in,
                              void* d_out, int out_size)
{
    const float* in    = (const float*)d_in[0];
    const float* INSC  = (const float*)d_in[1];
    const float* COEFF = (const float*)d_in[2];
    const float* SQ    = (const float*)d_in[3];
    const float* SMSC  = (const float*)d_in[4];
    const float* SUB   = (const float*)d_in[5];
    const float* CRAK  = (const float*)d_in[6];
    const float* RecK  = (const float*)d_in[7];
    float* out = (float*)d_out;

    constexpr int T = 1024;
    int B = out_size / T;
    int blocks = (B + 31) / 32;
    hirnn_kernel<T><<<blocks, 32>>>(in, INSC, COEFF, SQ, SMSC, SUB, CRAK, RecK,
                                    out, B);
}